// round 14
// baseline (speedup 1.0000x reference)
#include <cuda_runtime.h>
#include <cuda_fp16.h>
#include <cstdint>

// Problem dims
constexpr int CD    = 512;
constexpr int NB    = 16;
constexpr int NN    = 64;
constexpr int XROWS = NB * NN;        // 1024
constexpr int XEL   = XROWS * CD;     // 524288
constexpr int EROWS = NB * NN * NN;   // 65536
constexpr int WSZ   = CD * CD;        // 262144

// Scratch
__device__ float g_Vix[XEL];
__device__ float g_Vjx[XEL];
__device__ float g_Ujx[XEL];
__device__ float g_xWU[XEL];
__device__ float g_agg[XEL];
__device__ float g_x1 [XEL];
// fp16 weights: [0]=WE1 [1]=WE2 [2..5]=WA1,WB1,WV1,WU1 [6..9]=WA2,WB2,WV2,WU2
__device__ __half g_wh[10 * WSZ];

// ======================= helpers =======================
__device__ __forceinline__ uint32_t smem_u32(const void* p) {
    uint32_t a;
    asm("{ .reg .u64 t; cvta.to.shared.u64 t, %1; cvt.u32.u64 %0, t; }" : "=r"(a) : "l"(p));
    return a;
}
__device__ __forceinline__ void ldm_x4(uint32_t addr, uint32_t& r0, uint32_t& r1,
                                       uint32_t& r2, uint32_t& r3) {
    asm volatile("ldmatrix.sync.aligned.m8n8.x4.shared.b16 {%0,%1,%2,%3}, [%4];"
                 : "=r"(r0), "=r"(r1), "=r"(r2), "=r"(r3) : "r"(addr));
}
__device__ __forceinline__ void mma_f16(float* c, uint32_t a0, uint32_t a1, uint32_t a2,
                                        uint32_t a3, uint32_t b0, uint32_t b1) {
    asm volatile(
        "mma.sync.aligned.m16n8k16.row.col.f32.f16.f16.f32 "
        "{%0,%1,%2,%3}, {%4,%5,%6,%7}, {%8,%9}, {%0,%1,%2,%3};"
        : "+f"(c[0]), "+f"(c[1]), "+f"(c[2]), "+f"(c[3])
        : "r"(a0), "r"(a1), "r"(a2), "r"(a3), "r"(b0), "r"(b1));
}
__device__ __forceinline__ void sts64(uint32_t addr, uint32_t w0, uint32_t w1) {
    asm volatile("st.shared.v2.b32 [%0], {%1, %2};" :: "r"(addr), "r"(w0), "r"(w1) : "memory");
}
__device__ __forceinline__ void sts128(uint32_t addr, uint4 v) {
    asm volatile("st.shared.v4.b32 [%0], {%1, %2, %3, %4};"
                 :: "r"(addr), "r"(v.x), "r"(v.y), "r"(v.z), "r"(v.w) : "memory");
}
__device__ __forceinline__ void cp_async16(uint32_t smem, const void* g) {
    asm volatile("cp.async.cg.shared.global [%0], [%1], 16;" :: "r"(smem), "l"(g) : "memory");
}
#define CP_COMMIT()  asm volatile("cp.async.commit_group;" ::: "memory")
#define CP_WAIT_0()  asm volatile("cp.async.wait_group 0;" ::: "memory")

__device__ __forceinline__ uint32_t pack_h2(__half a, __half b) {
    __half2 t = __halves2half2(a, b);
    return *reinterpret_cast<uint32_t*>(&t);
}
__device__ __forceinline__ float warp_sum(float v) {
#pragma unroll
    for (int o = 16; o > 0; o >>= 1) v += __shfl_xor_sync(0xffffffffu, v, o);
    return v;
}

// ======================= kernel 0: fp16 weight convert =======================
extern "C" __global__ void wsplit10_kernel(
    const float* __restrict__ a0, const float* __restrict__ a1,
    const float* __restrict__ a2, const float* __restrict__ a3,
    const float* __restrict__ a4, const float* __restrict__ a5,
    const float* __restrict__ a6, const float* __restrict__ a7,
    const float* __restrict__ a8, const float* __restrict__ a9) {
    const float* srcs[10] = {a0, a1, a2, a3, a4, a5, a6, a7, a8, a9};
    const float* src = srcs[blockIdx.y];
    int idx = blockIdx.x * 256 + threadIdx.x;
    g_wh[(size_t)blockIdx.y * WSZ + idx] = __float2half_rn(src[idx]);
}

// ======================= x-GEMM (single fp16, 128x128 tiles) =================
constexpr int AST = 40;   // smem row stride (fp16)

extern "C" __global__ void __launch_bounds__(256, 2)
x_gemm_kernel(const float* __restrict__ A, const __half* __restrict__ Bh) {
    __shared__ __half s_a[128 * AST];
    __shared__ __half s_b[128 * AST];

    int tid = threadIdx.x, lane = tid & 31, wid = tid >> 5;
    int rowBase = blockIdx.x * 128;
    int colBase = blockIdx.y * 128;
    int wm = wid & 3, wn = wid >> 2;

    uint32_t ua = smem_u32(s_a);
    uint32_t ub = smem_u32(s_b);

    float acc[2][8][4];
#pragma unroll
    for (int mt = 0; mt < 2; mt++)
#pragma unroll
        for (int nt = 0; nt < 8; nt++)
#pragma unroll
            for (int q = 0; q < 4; q++) acc[mt][nt][q] = 0.f;

    int rr = tid >> 1, half = tid & 1;
    const float*  aptr = A  + (size_t)(rowBase + rr) * CD + half * 16;
    const __half* bptr = Bh + (size_t)(colBase + rr) * CD + half * 16;
    uint32_t soff = (uint32_t)(rr * AST + half * 16) * 2;

    for (int k0 = 0; k0 < CD; k0 += 32) {
        __syncthreads();
#pragma unroll
        for (int q = 0; q < 4; q++) {
            float4 v = *(const float4*)(aptr + k0 + q * 4);
            sts64(ua + soff + q * 8,
                  pack_h2(__float2half_rn(v.x), __float2half_rn(v.y)),
                  pack_h2(__float2half_rn(v.z), __float2half_rn(v.w)));
        }
#pragma unroll
        for (int q = 0; q < 2; q++)
            sts128(ub + soff + q * 16, *(const uint4*)(bptr + k0 + q * 8));
        __syncthreads();

#pragma unroll
        for (int kk = 0; kk < 2; kk++) {
            uint32_t b[8][2];
#pragma unroll
            for (int np = 0; np < 4; np++) {
                int n   = wn * 64 + np * 16 + (lane & 7) + ((lane >> 4) << 3);
                int kel = kk * 16 + (((lane >> 3) & 1) << 3);
                uint32_t r0, r1, r2, r3;
                ldm_x4(ub + (uint32_t)(n * AST + kel) * 2, r0, r1, r2, r3);
                b[np * 2][0] = r0; b[np * 2][1] = r1;
                b[np * 2 + 1][0] = r2; b[np * 2 + 1][1] = r3;
            }
            uint32_t a[2][4];
#pragma unroll
            for (int mt = 0; mt < 2; mt++) {
                int row = wm * 32 + mt * 16 + (lane & 15);
                int kel = kk * 16 + ((lane >> 4) << 3);
                ldm_x4(ua + (uint32_t)(row * AST + kel) * 2,
                       a[mt][0], a[mt][1], a[mt][2], a[mt][3]);
            }
#pragma unroll
            for (int mt = 0; mt < 2; mt++)
#pragma unroll
                for (int nt = 0; nt < 8; nt++)
                    mma_f16(acc[mt][nt], a[mt][0], a[mt][1], a[mt][2], a[mt][3],
                            b[nt][0], b[nt][1]);
        }
    }

    int r0 = wm * 32 + (lane >> 2);
    int c0 = wn * 64 + (lane & 3) * 2;
    const int mat = colBase >> 9;
    float* O = (mat == 0) ? g_Vix : (mat == 1) ? g_Vjx : (mat == 2) ? g_Ujx : g_xWU;
    int cb = colBase & 511;
#pragma unroll
    for (int mt = 0; mt < 2; mt++) {
        int gr = rowBase + r0 + mt * 16;
#pragma unroll
        for (int nt = 0; nt < 8; nt++) {
            int c = cb + c0 + nt * 8;
            *(float2*)&O[(size_t)gr * CD + c] = make_float2(acc[mt][nt][0], acc[mt][nt][1]);
            *(float2*)&O[(size_t)(gr + 8) * CD + c] = make_float2(acc[mt][nt][2], acc[mt][nt][3]);
        }
    }
}

// ============ fused edge GEMM + LN + residual + softmax-agg =================
// CTA: 64 rows = one full (b,i) j-block x 512 cols. 512 threads, 16 warps.
// Warp tile 32x64: wm = wid>>3, wn = wid&7. Single fp16 A (no split).
// Epilogue ALSO computes agg[b,i,c] = sum_j e*Ujx / (sum_j e * 64) where
// e = exp(sigmoid(eout)) (CTA holds all 64 j rows), writes g_agg.
constexpr int BST     = 40;                        // smem row stride (fp16)
constexpr int SB_SZ   = 512 * BST * 2;             // 40960 B per B stage
constexpr int SM_SB0  = 0;
constexpr int SM_SB1  = SB_SZ;                     // 40960
constexpr int SM_A    = 2 * SB_SZ;                 // 81920; 2 bufs of 5120
constexpr int A_SZ    = 64 * BST * 2;              // 5120
constexpr int SM_RED  = SM_A + 2 * A_SZ;           // 92160; float2[64][8]
constexpr int SM_SE   = SM_RED + 64 * 8 * 8;       // 96256; float[512]
constexpr int SM_SW   = SM_SE + 512 * 4;           // 98304; float[512]
constexpr int SMEM_EDGE = SM_SW + 512 * 4;         // 100352

extern "C" __global__ void __launch_bounds__(512, 1)
edge_fused_kernel(const float* __restrict__ Ein, const __half* __restrict__ Wh,
                  const float* __restrict__ ge, const float* __restrict__ be,
                  float* __restrict__ Eout) {
    extern __shared__ char smc[];
    uint32_t sb = smem_u32(smc);
    int tid = threadIdx.x, lane = tid & 31, wid = tid >> 5;
    int wm = wid >> 3, wn = wid & 7;
    int rowBase = blockIdx.x * 64;

    float acc[2][8][4];
#pragma unroll
    for (int mt = 0; mt < 2; mt++)
#pragma unroll
        for (int nt = 0; nt < 8; nt++)
#pragma unroll
            for (int q = 0; q < 4; q++) acc[mt][nt][q] = 0.f;

    int bu_n = tid >> 2, bu_k = tid & 3;         // B: n = bu_n + 128q
    int arow = tid >> 3, acol = (tid & 7) * 4;   // A: one float4 of 64x32 chunk
    const float* aptr = Ein + (size_t)(rowBase + arow) * CD + acol;
    uint32_t aoff = (uint32_t)(arow * BST + acol) * 2;

    // prologue: B chunk 0 + A chunk 0
#pragma unroll
    for (int q = 0; q < 4; q++) {
        int n = bu_n + q * 128;
        cp_async16(sb + SM_SB0 + (uint32_t)(n * BST + bu_k * 8) * 2,
                   Wh + (size_t)n * CD + bu_k * 8);
    }
    CP_COMMIT();
    float4 av = *(const float4*)(aptr);
    sts64(sb + SM_A + aoff,
          pack_h2(__float2half_rn(av.x), __float2half_rn(av.y)),
          pack_h2(__float2half_rn(av.z), __float2half_rn(av.w)));
    av = *(const float4*)(aptr + 32);
    CP_WAIT_0();
    __syncthreads();

    for (int ch = 0; ch < 16; ch++) {
        int cur = ch & 1, nxt = cur ^ 1;
        if (ch < 15) {
            uint32_t dst = sb + (nxt ? SM_SB1 : SM_SB0);
            const __half* src = Wh + (size_t)(ch + 1) * 32;
#pragma unroll
            for (int q = 0; q < 4; q++) {
                int n = bu_n + q * 128;
                cp_async16(dst + (uint32_t)(n * BST + bu_k * 8) * 2,
                           src + (size_t)n * CD + bu_k * 8);
            }
            CP_COMMIT();
            sts64(sb + SM_A + (uint32_t)nxt * A_SZ + aoff,
                  pack_h2(__float2half_rn(av.x), __float2half_rn(av.y)),
                  pack_h2(__float2half_rn(av.z), __float2half_rn(av.w)));
            if (ch < 14) av = *(const float4*)(aptr + (ch + 2) * 32);
        }

        uint32_t sbB = sb + (cur ? SM_SB1 : SM_SB0);
        uint32_t sA  = sb + SM_A + (uint32_t)cur * A_SZ;
#pragma unroll
        for (int kk = 0; kk < 2; kk++) {
            uint32_t b[4][4];
#pragma unroll
            for (int np = 0; np < 4; np++) {
                int n   = wn * 64 + np * 16 + (lane & 7) + ((lane >> 4) << 3);
                int kel = kk * 16 + (((lane >> 3) & 1) << 3);
                ldm_x4(sbB + (uint32_t)(n * BST + kel) * 2,
                       b[np][0], b[np][1], b[np][2], b[np][3]);
            }
            uint32_t a[2][4];
            int kel = kk * 16 + ((lane >> 4) << 3);
#pragma unroll
            for (int mt = 0; mt < 2; mt++) {
                int row = wm * 32 + mt * 16 + (lane & 15);
                ldm_x4(sA + (uint32_t)(row * BST + kel) * 2,
                       a[mt][0], a[mt][1], a[mt][2], a[mt][3]);
            }
#pragma unroll
            for (int mt = 0; mt < 2; mt++)
#pragma unroll
                for (int np = 0; np < 4; np++) {
                    mma_f16(acc[mt][np * 2],     a[mt][0], a[mt][1], a[mt][2], a[mt][3],
                            b[np][0], b[np][1]);
                    mma_f16(acc[mt][np * 2 + 1], a[mt][0], a[mt][1], a[mt][2], a[mt][3],
                            b[np][2], b[np][3]);
                }
        }
        CP_WAIT_0();
        __syncthreads();
    }

    // ---- epilogue pass 1: m = acc + Vix + Vjx; LN partial sums ----
    float2* s_red = (float2*)(smc + SM_RED);     // [row 0..63][wn 0..7]
    float*  s_se  = (float*) (smc + SM_SE);
    float*  s_sw  = (float*) (smc + SM_SW);
    s_se[tid & 511] = 0.f;                       // zero softmax accumulators
    s_sw[tid & 511] = 0.f;

    int r0 = lane >> 2;
    int c0 = wn * 64 + (lane & 3) * 2;
    int bI = rowBase >> 12, iI = (rowBase >> 6) & 63;
    const float* vix = g_Vix + (size_t)((bI << 6) + iI) * CD;

#pragma unroll
    for (int mt = 0; mt < 2; mt++)
#pragma unroll
        for (int h = 0; h < 2; h++) {
            int rloc = wm * 32 + mt * 16 + h * 8 + r0;
            const float* vjx = g_Vjx + (size_t)((bI << 6) + rloc) * CD;
            float sum = 0.f, ss = 0.f;
#pragma unroll
            for (int nt = 0; nt < 8; nt++) {
                int c = c0 + nt * 8;
                float2 vi = *(const float2*)&vix[c];
                float2 vj = *(const float2*)&vjx[c];
                float m0 = acc[mt][nt][h * 2 + 0] + vi.x + vj.x;
                float m1 = acc[mt][nt][h * 2 + 1] + vi.y + vj.y;
                acc[mt][nt][h * 2 + 0] = m0;
                acc[mt][nt][h * 2 + 1] = m1;
                sum += m0 + m1;
                ss  += m0 * m0 + m1 * m1;
            }
            sum += __shfl_xor_sync(0xffffffffu, sum, 1);
            sum += __shfl_xor_sync(0xffffffffu, sum, 2);
            ss  += __shfl_xor_sync(0xffffffffu, ss, 1);
            ss  += __shfl_xor_sync(0xffffffffu, ss, 2);
            if ((lane & 3) == 0) s_red[rloc * 8 + wn] = make_float2(sum, ss);
        }
    __syncthreads();

    // ---- epilogue pass 2: LN -> eout; accumulate softmax sums ----
    float se_acc[8][2], sw_acc[8][2];
#pragma unroll
    for (int nt = 0; nt < 8; nt++) {
        se_acc[nt][0] = se_acc[nt][1] = 0.f;
        sw_acc[nt][0] = sw_acc[nt][1] = 0.f;
    }

#pragma unroll
    for (int mt = 0; mt < 2; mt++)
#pragma unroll
        for (int h = 0; h < 2; h++) {
            int rloc = wm * 32 + mt * 16 + h * 8 + r0;
            int grow = rowBase + rloc;
            float sum = 0.f, ss = 0.f;
#pragma unroll
            for (int w = 0; w < 8; w++) {
                float2 pp = s_red[rloc * 8 + w];
                sum += pp.x; ss += pp.y;
            }
            float mean = sum * (1.f / CD);
            float var  = ss * (1.f / CD) - mean * mean;
            float inv  = rsqrtf(var + 1e-5f);
            const float* ein = Ein  + (size_t)grow * CD;
            const float* ujx = g_Ujx + (size_t)((bI << 6) + rloc) * CD;
            float*       eo  = Eout + (size_t)grow * CD;
#pragma unroll
            for (int nt = 0; nt < 8; nt++) {
                int c = c0 + nt * 8;
                float2 g  = *(const float2*)&ge[c];
                float2 bb = *(const float2*)&be[c];
                float2 e  = *(const float2*)&ein[c];
                float2 u  = *(const float2*)&ujx[c];
                float2 o;
                o.x = e.x + fmaxf((acc[mt][nt][h * 2 + 0] - mean) * inv * g.x + bb.x, 0.f);
                o.y = e.y + fmaxf((acc[mt][nt][h * 2 + 1] - mean) * inv * g.y + bb.y, 0.f);
                *(float2*)&eo[c] = o;
                float sg0 = __fdividef(1.f, 1.f + __expf(-o.x));
                float sg1 = __fdividef(1.f, 1.f + __expf(-o.y));
                float ex0 = __expf(sg0);
                float ex1 = __expf(sg1);
                se_acc[nt][0] += ex0;            se_acc[nt][1] += ex1;
                sw_acc[nt][0] = fmaf(ex0, u.x, sw_acc[nt][0]);
                sw_acc[nt][1] = fmaf(ex1, u.y, sw_acc[nt][1]);
            }
        }

    // reduce over the 8 in-warp rows (r0 = lane>>2) via xor-shfl 4/8/16
#pragma unroll
    for (int nt = 0; nt < 8; nt++)
#pragma unroll
        for (int p = 0; p < 2; p++) {
            float se = se_acc[nt][p], sw = sw_acc[nt][p];
#pragma unroll
            for (int o = 4; o <= 16; o <<= 1) {
                se += __shfl_xor_sync(0xffffffffu, se, o);
                sw += __shfl_xor_sync(0xffffffffu, sw, o);
            }
            if (lane < 4) {                      // one lane per (lane&3) column slot
                int c = c0 + nt * 8 + p;
                atomicAdd(&s_se[c], se);
                atomicAdd(&s_sw[c], sw);
            }
        }
    __syncthreads();

    // agg[b,i,c] = sw / (se * 64); one thread per channel (first 512 threads)
    {
        int c = tid;
        if (c < 512) {
            g_agg[(size_t)blockIdx.x * CD + c] =
                __fdividef(s_sw[c], s_se[c] * (float)NN);
        }
    }
}

// ======================= x update ===========================================
extern "C" __global__ void x_update_kernel(const float* __restrict__ xres,
                                           const float* __restrict__ gv,
                                           const float* __restrict__ bv,
                                           float* __restrict__ xout) {
    int warp = threadIdx.x >> 5, lane = threadIdx.x & 31;
    int row  = blockIdx.x * 8 + warp;
    const float* a  = g_xWU + (size_t)row * CD;
    const float* ag = g_agg + (size_t)row * CD;
    float t[16];
    float s = 0.f;
#pragma unroll
    for (int v = 0; v < 16; v++) {
        int c = lane + 32 * v;
        t[v]  = a[c] + ag[c];
        s += t[v];
    }
    s = warp_sum(s);
    float mean = s * (1.f / CD);
    float q = 0.f;
#pragma unroll
    for (int v = 0; v < 16; v++) { float d = t[v] - mean; q += d * d; }
    q = warp_sum(q);
    float inv = rsqrtf(q * (1.f / CD) + 1e-5f);
    const float* r = xres + (size_t)row * CD;
    float*       o = xout + (size_t)row * CD;
#pragma unroll
    for (int v = 0; v < 16; v++) {
        int c = lane + 32 * v;
        float val = (t[v] - mean) * inv * gv[c] + bv[c];
        o[c] = fmaxf(r[c] + val, 0.f);
    }
}

// ===========================================================================
extern "C" void kernel_launch(void* const* d_in, const int* in_sizes, int n_in,
                              void* d_out, int out_size) {
    const float* x    = (const float*)d_in[0];
    const float* edge = (const float*)d_in[1];
    const float* WA1  = (const float*)d_in[2];
    const float* WB1  = (const float*)d_in[3];
    const float* WE1  = (const float*)d_in[4];
    const float* WU1  = (const float*)d_in[5];
    const float* WV1  = (const float*)d_in[6];
    const float* WA2  = (const float*)d_in[7];
    const float* WB2  = (const float*)d_in[8];
    const float* WE2  = (const float*)d_in[9];
    const float* WU2  = (const float*)d_in[10];
    const float* WV2  = (const float*)d_in[11];
    const float* ge1  = (const float*)d_in[12];
    const float* gv1  = (const float*)d_in[13];
    const float* ge2  = (const float*)d_in[14];
    const float* gv2  = (const float*)d_in[15];
    const float* be1  = (const float*)d_in[16];
    const float* bv1  = (const float*)d_in[17];
    const float* be2  = (const float*)d_in[18];
    const float* bv2  = (const float*)d_in[19];

    float* xout = (float*)d_out;
    float* eout = (float*)d_out + XEL;

    void* p = nullptr;
    cudaGetSymbolAddress(&p, g_x1); float* x1 = (float*)p;
    cudaGetSymbolAddress(&p, g_wh); __half* wh = (__half*)p;

    cudaFuncSetAttribute(edge_fused_kernel,
                         cudaFuncAttributeMaxDynamicSharedMemorySize, SMEM_EDGE);

    wsplit10_kernel<<<dim3(WSZ / 256, 10), 256>>>(WE1, WE2,
        WA1, WB1, WV1, WU1, WA2, WB2, WV2, WU2);

    // ---- layer 1 ----
    x_gemm_kernel<<<dim3(XROWS / 128, 16), 256>>>(x, wh + 2 * (size_t)WSZ);
    edge_fused_kernel<<<EROWS / 64, 512, SMEM_EDGE>>>(edge, wh, ge1, be1, eout);
    x_update_kernel<<<XROWS / 8, 256>>>(x, gv1, bv1, x1);

    // ---- layer 2 (edge path in place on eout) ----
    x_gemm_kernel<<<dim3(XROWS / 128, 16), 256>>>(x1, wh + 6 * (size_t)WSZ);
    edge_fused_kernel<<<EROWS / 64, 512, SMEM_EDGE>>>(eout, wh + (size_t)WSZ, ge2, be2, eout);
    x_update_kernel<<<XROWS / 8, 256>>>(x1, gv2, bv2, xout);
}

// round 16
// speedup vs baseline: 1.4500x; 1.4500x over previous
#include <cuda_runtime.h>
#include <cuda_fp16.h>
#include <cstdint>

// Problem dims
constexpr int CD    = 512;
constexpr int NB    = 16;
constexpr int NN    = 64;
constexpr int XROWS = NB * NN;        // 1024
constexpr int XEL   = XROWS * CD;     // 524288
constexpr int EROWS = NB * NN * NN;   // 65536
constexpr int WSZ   = CD * CD;        // 262144

// Scratch
__device__ float g_Vix[XEL];
__device__ float g_Vjx[XEL];
__device__ float g_Ujx[XEL];
__device__ float g_xWU[XEL];
__device__ float g_x1 [XEL];
// fp16 weights: [0]=WE1 [1]=WE2 [2..5]=WA1,WB1,WV1,WU1 [6..9]=WA2,WB2,WV2,WU2
__device__ __half g_wh[10 * WSZ];

// ======================= helpers =======================
__device__ __forceinline__ uint32_t smem_u32(const void* p) {
    uint32_t a;
    asm("{ .reg .u64 t; cvta.to.shared.u64 t, %1; cvt.u32.u64 %0, t; }" : "=r"(a) : "l"(p));
    return a;
}
__device__ __forceinline__ void ldm_x4(uint32_t addr, uint32_t& r0, uint32_t& r1,
                                       uint32_t& r2, uint32_t& r3) {
    asm volatile("ldmatrix.sync.aligned.m8n8.x4.shared.b16 {%0,%1,%2,%3}, [%4];"
                 : "=r"(r0), "=r"(r1), "=r"(r2), "=r"(r3) : "r"(addr));
}
__device__ __forceinline__ void mma_f16(float* c, uint32_t a0, uint32_t a1, uint32_t a2,
                                        uint32_t a3, uint32_t b0, uint32_t b1) {
    asm volatile(
        "mma.sync.aligned.m16n8k16.row.col.f32.f16.f16.f32 "
        "{%0,%1,%2,%3}, {%4,%5,%6,%7}, {%8,%9}, {%0,%1,%2,%3};"
        : "+f"(c[0]), "+f"(c[1]), "+f"(c[2]), "+f"(c[3])
        : "r"(a0), "r"(a1), "r"(a2), "r"(a3), "r"(b0), "r"(b1));
}
__device__ __forceinline__ void sts64(uint32_t addr, uint32_t w0, uint32_t w1) {
    asm volatile("st.shared.v2.b32 [%0], {%1, %2};" :: "r"(addr), "r"(w0), "r"(w1) : "memory");
}
__device__ __forceinline__ void sts128(uint32_t addr, uint4 v) {
    asm volatile("st.shared.v4.b32 [%0], {%1, %2, %3, %4};"
                 :: "r"(addr), "r"(v.x), "r"(v.y), "r"(v.z), "r"(v.w) : "memory");
}
__device__ __forceinline__ void cp_async16(uint32_t smem, const void* g) {
    asm volatile("cp.async.cg.shared.global [%0], [%1], 16;" :: "r"(smem), "l"(g) : "memory");
}
#define CP_COMMIT()  asm volatile("cp.async.commit_group;" ::: "memory")
#define CP_WAIT_0()  asm volatile("cp.async.wait_group 0;" ::: "memory")

__device__ __forceinline__ uint32_t pack_h2(__half a, __half b) {
    __half2 t = __halves2half2(a, b);
    return *reinterpret_cast<uint32_t*>(&t);
}
__device__ __forceinline__ float warp_sum(float v) {
#pragma unroll
    for (int o = 16; o > 0; o >>= 1) v += __shfl_xor_sync(0xffffffffu, v, o);
    return v;
}

// ======================= kernel 0: fp16 weight convert =======================
extern "C" __global__ void wsplit10_kernel(
    const float* __restrict__ a0, const float* __restrict__ a1,
    const float* __restrict__ a2, const float* __restrict__ a3,
    const float* __restrict__ a4, const float* __restrict__ a5,
    const float* __restrict__ a6, const float* __restrict__ a7,
    const float* __restrict__ a8, const float* __restrict__ a9) {
    const float* srcs[10] = {a0, a1, a2, a3, a4, a5, a6, a7, a8, a9};
    const float* src = srcs[blockIdx.y];
    int idx = blockIdx.x * 256 + threadIdx.x;
    g_wh[(size_t)blockIdx.y * WSZ + idx] = __float2half_rn(src[idx]);
}

// ======================= x-GEMM (single fp16, 128x128 tiles) =================
constexpr int AST = 40;   // smem row stride (fp16)

extern "C" __global__ void __launch_bounds__(256, 2)
x_gemm_kernel(const float* __restrict__ A, const __half* __restrict__ Bh) {
    __shared__ __half s_a[128 * AST];
    __shared__ __half s_b[128 * AST];

    int tid = threadIdx.x, lane = tid & 31, wid = tid >> 5;
    int rowBase = blockIdx.x * 128;
    int colBase = blockIdx.y * 128;
    int wm = wid & 3, wn = wid >> 2;

    uint32_t ua = smem_u32(s_a);
    uint32_t ub = smem_u32(s_b);

    float acc[2][8][4];
#pragma unroll
    for (int mt = 0; mt < 2; mt++)
#pragma unroll
        for (int nt = 0; nt < 8; nt++)
#pragma unroll
            for (int q = 0; q < 4; q++) acc[mt][nt][q] = 0.f;

    int rr = tid >> 1, half = tid & 1;
    const float*  aptr = A  + (size_t)(rowBase + rr) * CD + half * 16;
    const __half* bptr = Bh + (size_t)(colBase + rr) * CD + half * 16;
    uint32_t soff = (uint32_t)(rr * AST + half * 16) * 2;

    for (int k0 = 0; k0 < CD; k0 += 32) {
        __syncthreads();
#pragma unroll
        for (int q = 0; q < 4; q++) {
            float4 v = *(const float4*)(aptr + k0 + q * 4);
            sts64(ua + soff + q * 8,
                  pack_h2(__float2half_rn(v.x), __float2half_rn(v.y)),
                  pack_h2(__float2half_rn(v.z), __float2half_rn(v.w)));
        }
#pragma unroll
        for (int q = 0; q < 2; q++)
            sts128(ub + soff + q * 16, *(const uint4*)(bptr + k0 + q * 8));
        __syncthreads();

#pragma unroll
        for (int kk = 0; kk < 2; kk++) {
            uint32_t b[8][2];
#pragma unroll
            for (int np = 0; np < 4; np++) {
                int n   = wn * 64 + np * 16 + (lane & 7) + ((lane >> 4) << 3);
                int kel = kk * 16 + (((lane >> 3) & 1) << 3);
                uint32_t r0, r1, r2, r3;
                ldm_x4(ub + (uint32_t)(n * AST + kel) * 2, r0, r1, r2, r3);
                b[np * 2][0] = r0; b[np * 2][1] = r1;
                b[np * 2 + 1][0] = r2; b[np * 2 + 1][1] = r3;
            }
            uint32_t a[2][4];
#pragma unroll
            for (int mt = 0; mt < 2; mt++) {
                int row = wm * 32 + mt * 16 + (lane & 15);
                int kel = kk * 16 + ((lane >> 4) << 3);
                ldm_x4(ua + (uint32_t)(row * AST + kel) * 2,
                       a[mt][0], a[mt][1], a[mt][2], a[mt][3]);
            }
#pragma unroll
            for (int mt = 0; mt < 2; mt++)
#pragma unroll
                for (int nt = 0; nt < 8; nt++)
                    mma_f16(acc[mt][nt], a[mt][0], a[mt][1], a[mt][2], a[mt][3],
                            b[nt][0], b[nt][1]);
        }
    }

    int r0 = wm * 32 + (lane >> 2);
    int c0 = wn * 64 + (lane & 3) * 2;
    const int mat = colBase >> 9;
    float* O = (mat == 0) ? g_Vix : (mat == 1) ? g_Vjx : (mat == 2) ? g_Ujx : g_xWU;
    int cb = colBase & 511;
#pragma unroll
    for (int mt = 0; mt < 2; mt++) {
        int gr = rowBase + r0 + mt * 16;
#pragma unroll
        for (int nt = 0; nt < 8; nt++) {
            int c = cb + c0 + nt * 8;
            *(float2*)&O[(size_t)gr * CD + c] = make_float2(acc[mt][nt][0], acc[mt][nt][1]);
            *(float2*)&O[(size_t)(gr + 8) * CD + c] = make_float2(acc[mt][nt][2], acc[mt][nt][3]);
        }
    }
}

// ======================= fused edge GEMM + LN + residual =====================
// CTA: 32 rows x 512 cols, 2 CTA/SM. 8 warps, warp tile 32 rows x 64 cols.
// Single fp16 A (no hi/lo split). A smem-double-buffered; B cp.async 2-stage.
constexpr int BST     = 40;                        // smem row stride (fp16)
constexpr int SB_SZ   = 512 * BST * 2;             // 40960 B per B stage
constexpr int SM_SB0  = 0;
constexpr int SM_SB1  = SB_SZ;                     // 40960
constexpr int SM_A    = 2 * SB_SZ;                 // 81920; 2 bufs of 2560
constexpr int A_SZ    = 32 * BST * 2;              // 2560
constexpr int SM_RED  = SM_A + 2 * A_SZ;           // 87040
constexpr int SMEM_EDGE = SM_RED + 32 * 8 * 8;     // + float2[32][8] = 89088

extern "C" __global__ void __launch_bounds__(256, 2)
edge_fused_kernel(const float* __restrict__ Ein, const __half* __restrict__ Wh,
                  const float* __restrict__ ge, const float* __restrict__ be,
                  float* __restrict__ Eout) {
    extern __shared__ char smc[];
    uint32_t sb = smem_u32(smc);
    int tid = threadIdx.x, lane = tid & 31, wn = tid >> 5;
    int rowBase = blockIdx.x * 32;

    float acc[2][8][4];
#pragma unroll
    for (int mt = 0; mt < 2; mt++)
#pragma unroll
        for (int nt = 0; nt < 8; nt++)
#pragma unroll
            for (int q = 0; q < 4; q++) acc[mt][nt][q] = 0.f;

    int bu_n = tid >> 2, bu_k = tid & 3;         // B: n = bu_n + 64q
    int arow = tid >> 3, acol = (tid & 7) * 4;   // A: one float4 of the 32x32 chunk
    const float* aptr = Ein + (size_t)(rowBase + arow) * CD + acol;
    uint32_t aoff = (uint32_t)(arow * BST + acol) * 2;

    // prologue: B chunk 0 + A chunk 0
#pragma unroll
    for (int q = 0; q < 8; q++) {
        int n = bu_n + q * 64;
        cp_async16(sb + SM_SB0 + (uint32_t)(n * BST + bu_k * 8) * 2,
                   Wh + (size_t)n * CD + bu_k * 8);
    }
    CP_COMMIT();
    float4 av = *(const float4*)(aptr);
    sts64(sb + SM_A + aoff,
          pack_h2(__float2half_rn(av.x), __float2half_rn(av.y)),
          pack_h2(__float2half_rn(av.z), __float2half_rn(av.w)));
    av = *(const float4*)(aptr + 32);
    CP_WAIT_0();
    __syncthreads();

    for (int ch = 0; ch < 16; ch++) {
        int cur = ch & 1, nxt = cur ^ 1;
        // issue B(ch+1) into the stage freed by MMA(ch-1); store A(ch+1)
        if (ch < 15) {
            uint32_t dst = sb + (nxt ? SM_SB1 : SM_SB0);
            const __half* src = Wh + (size_t)(ch + 1) * 32;
#pragma unroll
            for (int q = 0; q < 8; q++) {
                int n = bu_n + q * 64;
                cp_async16(dst + (uint32_t)(n * BST + bu_k * 8) * 2,
                           src + (size_t)n * CD + bu_k * 8);
            }
            CP_COMMIT();
            sts64(sb + SM_A + (uint32_t)nxt * A_SZ + aoff,
                  pack_h2(__float2half_rn(av.x), __float2half_rn(av.y)),
                  pack_h2(__float2half_rn(av.z), __float2half_rn(av.w)));
            if (ch < 14) av = *(const float4*)(aptr + (ch + 2) * 32);
        }

        uint32_t sbB = sb + (cur ? SM_SB1 : SM_SB0);
        uint32_t sA  = sb + SM_A + (uint32_t)cur * A_SZ;
#pragma unroll
        for (int kk = 0; kk < 2; kk++) {
            uint32_t b[4][4];
#pragma unroll
            for (int np = 0; np < 4; np++) {
                int n   = wn * 64 + np * 16 + (lane & 7) + ((lane >> 4) << 3);
                int kel = kk * 16 + (((lane >> 3) & 1) << 3);
                ldm_x4(sbB + (uint32_t)(n * BST + kel) * 2,
                       b[np][0], b[np][1], b[np][2], b[np][3]);
            }
            uint32_t a[2][4];
            int kel = kk * 16 + ((lane >> 4) << 3);
#pragma unroll
            for (int mt = 0; mt < 2; mt++) {
                int row = mt * 16 + (lane & 15);
                ldm_x4(sA + (uint32_t)(row * BST + kel) * 2,
                       a[mt][0], a[mt][1], a[mt][2], a[mt][3]);
            }
#pragma unroll
            for (int mt = 0; mt < 2; mt++)
#pragma unroll
                for (int np = 0; np < 4; np++) {
                    mma_f16(acc[mt][np * 2],     a[mt][0], a[mt][1], a[mt][2], a[mt][3],
                            b[np][0], b[np][1]);
                    mma_f16(acc[mt][np * 2 + 1], a[mt][0], a[mt][1], a[mt][2], a[mt][3],
                            b[np][2], b[np][3]);
                }
        }
        CP_WAIT_0();
        __syncthreads();
    }

    // ---- fused epilogue ----
    float2* s_red = (float2*)(smc + SM_RED);     // [row 0..31][wn 0..7]
    int r0 = lane >> 2;
    int c0 = wn * 64 + (lane & 3) * 2;
    int bI = rowBase >> 12, iI = (rowBase >> 6) & 63;
    const float* vix = g_Vix + (size_t)((bI << 6) + iI) * CD;

#pragma unroll
    for (int mt = 0; mt < 2; mt++)
#pragma unroll
        for (int h = 0; h < 2; h++) {
            int rloc = mt * 16 + h * 8 + r0;
            int grow = rowBase + rloc;
            const float* vjx = g_Vjx + (size_t)((bI << 6) + (grow & 63)) * CD;
            float sum = 0.f, ss = 0.f;
#pragma unroll
            for (int nt = 0; nt < 8; nt++) {
                int c = c0 + nt * 8;
                float2 vi = *(const float2*)&vix[c];
                float2 vj = *(const float2*)&vjx[c];
                float m0 = acc[mt][nt][h * 2 + 0] + vi.x + vj.x;
                float m1 = acc[mt][nt][h * 2 + 1] + vi.y + vj.y;
                acc[mt][nt][h * 2 + 0] = m0;
                acc[mt][nt][h * 2 + 1] = m1;
                sum += m0 + m1;
                ss  += m0 * m0 + m1 * m1;
            }
            sum += __shfl_xor_sync(0xffffffffu, sum, 1);
            sum += __shfl_xor_sync(0xffffffffu, sum, 2);
            ss  += __shfl_xor_sync(0xffffffffu, ss, 1);
            ss  += __shfl_xor_sync(0xffffffffu, ss, 2);
            if ((lane & 3) == 0) s_red[rloc * 8 + wn] = make_float2(sum, ss);
        }
    __syncthreads();

#pragma unroll
    for (int mt = 0; mt < 2; mt++)
#pragma unroll
        for (int h = 0; h < 2; h++) {
            int rloc = mt * 16 + h * 8 + r0;
            int grow = rowBase + rloc;
            float sum = 0.f, ss = 0.f;
#pragma unroll
            for (int w = 0; w < 8; w++) {
                float2 pp = s_red[rloc * 8 + w];
                sum += pp.x; ss += pp.y;
            }
            float mean = sum * (1.f / CD);
            float var  = ss * (1.f / CD) - mean * mean;
            float inv  = rsqrtf(var + 1e-5f);
            const float* ein = Ein  + (size_t)grow * CD;
            float*       eo  = Eout + (size_t)grow * CD;
#pragma unroll
            for (int nt = 0; nt < 8; nt++) {
                int c = c0 + nt * 8;
                float2 g  = *(const float2*)&ge[c];
                float2 bb = *(const float2*)&be[c];
                float2 e  = *(const float2*)&ein[c];
                float2 o;
                o.x = e.x + fmaxf((acc[mt][nt][h * 2 + 0] - mean) * inv * g.x + bb.x, 0.f);
                o.y = e.y + fmaxf((acc[mt][nt][h * 2 + 1] - mean) * inv * g.y + bb.y, 0.f);
                *(float2*)&eo[c] = o;
            }
        }
}

// ============== fused softmax-over-j + agg + x LN update ====================
// block = (b,i); 256 threads, each owns channels c and c+256.
extern "C" __global__ void __launch_bounds__(256)
softmax_x_kernel(const float* __restrict__ E, const float* __restrict__ xres,
                 const float* __restrict__ gv, const float* __restrict__ bv,
                 float* __restrict__ xout) {
    __shared__ float s_sum[8], s_ss[8];
    int bi = blockIdx.x;
    int b  = bi >> 6;
    int c  = threadIdx.x;
    const float* ep = E     + (size_t)bi * NN * CD + c;
    const float* up = g_Ujx + (size_t)b  * NN * CD + c;
    float se0 = 0.f, sw0 = 0.f, se1 = 0.f, sw1 = 0.f;
#pragma unroll 4
    for (int j = 0; j < NN; j++) {
        float v0  = ep[(size_t)j * CD];
        float v1  = ep[(size_t)j * CD + 256];
        float sg0 = __fdividef(1.f, 1.f + __expf(-v0));
        float sg1 = __fdividef(1.f, 1.f + __expf(-v1));
        float e0  = __expf(sg0);
        float e1  = __expf(sg1);
        se0 += e0; se1 += e1;
        sw0 = fmaf(e0, up[(size_t)j * CD], sw0);
        sw1 = fmaf(e1, up[(size_t)j * CD + 256], sw1);
    }
    const float* a = g_xWU + (size_t)bi * CD;
    float t0 = a[c]       + __fdividef(sw0, se0 * (float)NN);
    float t1 = a[c + 256] + __fdividef(sw1, se1 * (float)NN);

    float sum = warp_sum(t0 + t1);
    float ss  = warp_sum(t0 * t0 + t1 * t1);
    int lane = c & 31, wid = c >> 5;
    if (lane == 0) { s_sum[wid] = sum; s_ss[wid] = ss; }
    __syncthreads();
    sum = 0.f; ss = 0.f;
#pragma unroll
    for (int w = 0; w < 8; w++) { sum += s_sum[w]; ss += s_ss[w]; }
    float mean = sum * (1.f / CD);
    float var  = ss * (1.f / CD) - mean * mean;
    float inv  = rsqrtf(var + 1e-5f);
    const float* r = xres + (size_t)bi * CD;
    float*       o = xout + (size_t)bi * CD;
    float v0 = (t0 - mean) * inv * gv[c]       + bv[c];
    float v1 = (t1 - mean) * inv * gv[c + 256] + bv[c + 256];
    o[c]       = fmaxf(r[c]       + v0, 0.f);
    o[c + 256] = fmaxf(r[c + 256] + v1, 0.f);
}

// ===========================================================================
extern "C" void kernel_launch(void* const* d_in, const int* in_sizes, int n_in,
                              void* d_out, int out_size) {
    const float* x    = (const float*)d_in[0];
    const float* edge = (const float*)d_in[1];
    const float* WA1  = (const float*)d_in[2];
    const float* WB1  = (const float*)d_in[3];
    const float* WE1  = (const float*)d_in[4];
    const float* WU1  = (const float*)d_in[5];
    const float* WV1  = (const float*)d_in[6];
    const float* WA2  = (const float*)d_in[7];
    const float* WB2  = (const float*)d_in[8];
    const float* WE2  = (const float*)d_in[9];
    const float* WU2  = (const float*)d_in[10];
    const float* WV2  = (const float*)d_in[11];
    const float* ge1  = (const float*)d_in[12];
    const float* gv1  = (const float*)d_in[13];
    const float* ge2  = (const float*)d_in[14];
    const float* gv2  = (const float*)d_in[15];
    const float* be1  = (const float*)d_in[16];
    const float* bv1  = (const float*)d_in[17];
    const float* be2  = (const float*)d_in[18];
    const float* bv2  = (const float*)d_in[19];

    float* xout = (float*)d_out;
    float* eout = (float*)d_out + XEL;

    void* p = nullptr;
    cudaGetSymbolAddress(&p, g_x1); float* x1 = (float*)p;
    cudaGetSymbolAddress(&p, g_wh); __half* wh = (__half*)p;

    cudaFuncSetAttribute(edge_fused_kernel,
                         cudaFuncAttributeMaxDynamicSharedMemorySize, SMEM_EDGE);

    wsplit10_kernel<<<dim3(WSZ / 256, 10), 256>>>(WE1, WE2,
        WA1, WB1, WV1, WU1, WA2, WB2, WV2, WU2);

    // ---- layer 1 ----
    x_gemm_kernel<<<dim3(XROWS / 128, 16), 256>>>(x, wh + 2 * (size_t)WSZ);
    edge_fused_kernel<<<EROWS / 32, 256, SMEM_EDGE>>>(edge, wh, ge1, be1, eout);
    softmax_x_kernel<<<XROWS, 256>>>(eout, x, gv1, bv1, x1);

    // ---- layer 2 (edge path in place on eout) ----
    x_gemm_kernel<<<dim3(XROWS / 128, 16), 256>>>(x1, wh + 6 * (size_t)WSZ);
    edge_fused_kernel<<<EROWS / 32, 256, SMEM_EDGE>>>(eout, wh + (size_t)WSZ, ge2, be2, eout);
    softmax_x_kernel<<<XROWS, 256>>>(eout, x1, gv2, bv2, xout);
}

// round 17
// speedup vs baseline: 1.8212x; 1.2560x over previous
#include <cuda_runtime.h>
#include <cuda_fp16.h>
#include <cstdint>

// Problem dims
constexpr int CD    = 512;
constexpr int NB    = 16;
constexpr int NN    = 64;
constexpr int XROWS = NB * NN;        // 1024
constexpr int XEL   = XROWS * CD;     // 524288
constexpr int EROWS = NB * NN * NN;   // 65536
constexpr int WSZ   = CD * CD;        // 262144

// Scratch
__device__ float g_Vix[XEL];
__device__ float g_Vjx[XEL];
__device__ float g_Ujx[XEL];
__device__ float g_xWU[XEL];
__device__ float g_x1 [XEL];
// fp16 x-weights (linear): [2..5]=WA1,WB1,WV1,WU1 [6..9]=WA2,WB2,WV2,WU2 (slots 0,1 unused)
__device__ __half g_wh[10 * WSZ];
// WE in chunk-tiled padded layout: [layer][chunk 0..15][n 0..511][40 fp16]
constexpr int WE_CH = 512 * 40;                  // halfs per chunk (20480)
__device__ __half g_weT[2 * 16 * WE_CH];

// ======================= helpers =======================
__device__ __forceinline__ uint32_t smem_u32(const void* p) {
    uint32_t a;
    asm("{ .reg .u64 t; cvta.to.shared.u64 t, %1; cvt.u32.u64 %0, t; }" : "=r"(a) : "l"(p));
    return a;
}
__device__ __forceinline__ void ldm_x4(uint32_t addr, uint32_t& r0, uint32_t& r1,
                                       uint32_t& r2, uint32_t& r3) {
    asm volatile("ldmatrix.sync.aligned.m8n8.x4.shared.b16 {%0,%1,%2,%3}, [%4];"
                 : "=r"(r0), "=r"(r1), "=r"(r2), "=r"(r3) : "r"(addr));
}
__device__ __forceinline__ void mma_f16(float* c, uint32_t a0, uint32_t a1, uint32_t a2,
                                        uint32_t a3, uint32_t b0, uint32_t b1) {
    asm volatile(
        "mma.sync.aligned.m16n8k16.row.col.f32.f16.f16.f32 "
        "{%0,%1,%2,%3}, {%4,%5,%6,%7}, {%8,%9}, {%0,%1,%2,%3};"
        : "+f"(c[0]), "+f"(c[1]), "+f"(c[2]), "+f"(c[3])
        : "r"(a0), "r"(a1), "r"(a2), "r"(a3), "r"(b0), "r"(b1));
}
__device__ __forceinline__ void sts64(uint32_t addr, uint32_t w0, uint32_t w1) {
    asm volatile("st.shared.v2.b32 [%0], {%1, %2};" :: "r"(addr), "r"(w0), "r"(w1) : "memory");
}
__device__ __forceinline__ void sts128(uint32_t addr, uint4 v) {
    asm volatile("st.shared.v4.b32 [%0], {%1, %2, %3, %4};"
                 :: "r"(addr), "r"(v.x), "r"(v.y), "r"(v.z), "r"(v.w) : "memory");
}
__device__ __forceinline__ void cp_async16(uint32_t smem, const void* g) {
    asm volatile("cp.async.cg.shared.global [%0], [%1], 16;" :: "r"(smem), "l"(g) : "memory");
}
#define CP_COMMIT()  asm volatile("cp.async.commit_group;" ::: "memory")
#define CP_WAIT_0()  asm volatile("cp.async.wait_group 0;" ::: "memory")

// bulk async copy gmem -> smem with mbarrier completion (sm_90 mainline)
__device__ __forceinline__ void cp_bulk(uint32_t smem_dst, const void* gsrc,
                                        uint32_t bytes, uint32_t mbar) {
    asm volatile(
        "cp.async.bulk.shared::cta.global.mbarrier::complete_tx::bytes "
        "[%0], [%1], %2, [%3];"
        :: "r"(smem_dst), "l"(gsrc), "r"(bytes), "r"(mbar) : "memory");
}
__device__ __forceinline__ void mbar_init(uint32_t mbar, uint32_t cnt) {
    asm volatile("mbarrier.init.shared.b64 [%0], %1;" :: "r"(mbar), "r"(cnt) : "memory");
}
__device__ __forceinline__ void mbar_expect_tx(uint32_t mbar, uint32_t bytes) {
    asm volatile("mbarrier.arrive.expect_tx.shared.b64 _, [%0], %1;"
                 :: "r"(mbar), "r"(bytes) : "memory");
}
__device__ __forceinline__ void mbar_wait(uint32_t mbar, uint32_t parity) {
    asm volatile("{\n\t.reg .pred P1;\n\t"
                 "WAIT_LOOP_%=:\n\t"
                 "mbarrier.try_wait.parity.acquire.cta.shared::cta.b64 P1, [%0], %1, 0x989680;\n\t"
                 "@P1 bra.uni WAIT_DONE_%=;\n\t"
                 "bra.uni WAIT_LOOP_%=;\n\t"
                 "WAIT_DONE_%=:\n\t}"
                 :: "r"(mbar), "r"(parity) : "memory");
}

__device__ __forceinline__ uint32_t pack_h2(__half a, __half b) {
    __half2 t = __halves2half2(a, b);
    return *reinterpret_cast<uint32_t*>(&t);
}
__device__ __forceinline__ float warp_sum(float v) {
#pragma unroll
    for (int o = 16; o > 0; o >>= 1) v += __shfl_xor_sync(0xffffffffu, v, o);
    return v;
}

// ======================= kernel 0a: fp16 x-weight convert ====================
extern "C" __global__ void wsplit10_kernel(
    const float* __restrict__ a0, const float* __restrict__ a1,
    const float* __restrict__ a2, const float* __restrict__ a3,
    const float* __restrict__ a4, const float* __restrict__ a5,
    const float* __restrict__ a6, const float* __restrict__ a7,
    const float* __restrict__ a8, const float* __restrict__ a9) {
    const float* srcs[10] = {a0, a1, a2, a3, a4, a5, a6, a7, a8, a9};
    const float* src = srcs[blockIdx.y];
    int idx = blockIdx.x * 256 + threadIdx.x;
    g_wh[(size_t)blockIdx.y * WSZ + idx] = __float2half_rn(src[idx]);
}

// ======================= kernel 0b: WE -> chunk-tiled fp16 ===================
// dst[layer][k>>5][n][k&31], row stride 40 halfs (pad 32..39 unread)
extern "C" __global__ void wsplit_we_kernel(const float* __restrict__ W1,
                                            const float* __restrict__ W2) {
    int layer = blockIdx.y;
    const float* src = layer ? W2 : W1;
    int idx = blockIdx.x * 256 + threadIdx.x;      // n*512 + k
    int n = idx >> 9, k = idx & 511;
    g_weT[(size_t)layer * 16 * WE_CH + (k >> 5) * WE_CH + n * 40 + (k & 31)] =
        __float2half_rn(src[idx]);
}

// ======================= x-GEMM (single fp16, 128x128 tiles) =================
constexpr int AST = 40;   // smem row stride (fp16)

extern "C" __global__ void __launch_bounds__(256, 2)
x_gemm_kernel(const float* __restrict__ A, const __half* __restrict__ Bh) {
    __shared__ __half s_a[128 * AST];
    __shared__ __half s_b[128 * AST];

    int tid = threadIdx.x, lane = tid & 31, wid = tid >> 5;
    int rowBase = blockIdx.x * 128;
    int colBase = blockIdx.y * 128;
    int wm = wid & 3, wn = wid >> 2;

    uint32_t ua = smem_u32(s_a);
    uint32_t ub = smem_u32(s_b);

    float acc[2][8][4];
#pragma unroll
    for (int mt = 0; mt < 2; mt++)
#pragma unroll
        for (int nt = 0; nt < 8; nt++)
#pragma unroll
            for (int q = 0; q < 4; q++) acc[mt][nt][q] = 0.f;

    int rr = tid >> 1, half = tid & 1;
    const float*  aptr = A  + (size_t)(rowBase + rr) * CD + half * 16;
    const __half* bptr = Bh + (size_t)(colBase + rr) * CD + half * 16;
    uint32_t soff = (uint32_t)(rr * AST + half * 16) * 2;

    for (int k0 = 0; k0 < CD; k0 += 32) {
        __syncthreads();
#pragma unroll
        for (int q = 0; q < 4; q++) {
            float4 v = *(const float4*)(aptr + k0 + q * 4);
            sts64(ua + soff + q * 8,
                  pack_h2(__float2half_rn(v.x), __float2half_rn(v.y)),
                  pack_h2(__float2half_rn(v.z), __float2half_rn(v.w)));
        }
#pragma unroll
        for (int q = 0; q < 2; q++)
            sts128(ub + soff + q * 16, *(const uint4*)(bptr + k0 + q * 8));
        __syncthreads();

#pragma unroll
        for (int kk = 0; kk < 2; kk++) {
            uint32_t b[8][2];
#pragma unroll
            for (int np = 0; np < 4; np++) {
                int n   = wn * 64 + np * 16 + (lane & 7) + ((lane >> 4) << 3);
                int kel = kk * 16 + (((lane >> 3) & 1) << 3);
                uint32_t r0, r1, r2, r3;
                ldm_x4(ub + (uint32_t)(n * AST + kel) * 2, r0, r1, r2, r3);
                b[np * 2][0] = r0; b[np * 2][1] = r1;
                b[np * 2 + 1][0] = r2; b[np * 2 + 1][1] = r3;
            }
            uint32_t a[2][4];
#pragma unroll
            for (int mt = 0; mt < 2; mt++) {
                int row = wm * 32 + mt * 16 + (lane & 15);
                int kel = kk * 16 + ((lane >> 4) << 3);
                ldm_x4(ua + (uint32_t)(row * AST + kel) * 2,
                       a[mt][0], a[mt][1], a[mt][2], a[mt][3]);
            }
#pragma unroll
            for (int mt = 0; mt < 2; mt++)
#pragma unroll
                for (int nt = 0; nt < 8; nt++)
                    mma_f16(acc[mt][nt], a[mt][0], a[mt][1], a[mt][2], a[mt][3],
                            b[nt][0], b[nt][1]);
        }
    }

    int r0 = wm * 32 + (lane >> 2);
    int c0 = wn * 64 + (lane & 3) * 2;
    const int mat = colBase >> 9;
    float* O = (mat == 0) ? g_Vix : (mat == 1) ? g_Vjx : (mat == 2) ? g_Ujx : g_xWU;
    int cb = colBase & 511;
#pragma unroll
    for (int mt = 0; mt < 2; mt++) {
        int gr = rowBase + r0 + mt * 16;
#pragma unroll
        for (int nt = 0; nt < 8; nt++) {
            int c = cb + c0 + nt * 8;
            *(float2*)&O[(size_t)gr * CD + c] = make_float2(acc[mt][nt][0], acc[mt][nt][1]);
            *(float2*)&O[(size_t)(gr + 8) * CD + c] = make_float2(acc[mt][nt][2], acc[mt][nt][3]);
        }
    }
}

// ======================= fused edge GEMM + LN + residual =====================
// CTA: 32 rows x 512 cols, 2 CTA/SM. 8 warps, warp tile 32 rows x 64 cols.
// B loaded via ONE cp.async.bulk (40960 B) per chunk, mbarrier completion.
constexpr int BST     = 40;                        // smem row stride (fp16)
constexpr int SB_SZ   = 512 * BST * 2;             // 40960 B per B stage
constexpr int SM_SB0  = 0;
constexpr int SM_SB1  = SB_SZ;                     // 40960
constexpr int SM_A    = 2 * SB_SZ;                 // 81920; 2 bufs of 2560
constexpr int A_SZ    = 32 * BST * 2;              // 2560
constexpr int SM_RED  = SM_A + 2 * A_SZ;           // 87040; float2[32][8]
constexpr int SM_MBAR = SM_RED + 32 * 8 * 8;       // 89088; 2 x 8B mbarriers
constexpr int SMEM_EDGE = SM_MBAR + 16;            // 89104

extern "C" __global__ void __launch_bounds__(256, 2)
edge_fused_kernel(const float* __restrict__ Ein, const __half* __restrict__ WhT,
                  const float* __restrict__ ge, const float* __restrict__ be,
                  float* __restrict__ Eout) {
    extern __shared__ char smc[];
    uint32_t sb = smem_u32(smc);
    int tid = threadIdx.x, lane = tid & 31, wn = tid >> 5;
    int rowBase = blockIdx.x * 32;

    float acc[2][8][4];
#pragma unroll
    for (int mt = 0; mt < 2; mt++)
#pragma unroll
        for (int nt = 0; nt < 8; nt++)
#pragma unroll
            for (int q = 0; q < 4; q++) acc[mt][nt][q] = 0.f;

    int arow = tid >> 3, acol = (tid & 7) * 4;   // A: one float4 of the 32x32 chunk
    const float* aptr = Ein + (size_t)(rowBase + arow) * CD + acol;
    uint32_t aoff = (uint32_t)(arow * BST + acol) * 2;

    // init mbarriers (arrive count 1: the expect_tx producer)
    if (tid == 0) {
        mbar_init(sb + SM_MBAR, 1);
        mbar_init(sb + SM_MBAR + 8, 1);
    }
    __syncthreads();

    // prologue: bulk B chunk 0 + A chunk 0
    if (tid == 0) {
        mbar_expect_tx(sb + SM_MBAR, SB_SZ);
        cp_bulk(sb + SM_SB0, WhT, SB_SZ, sb + SM_MBAR);
    }
    float4 av = *(const float4*)(aptr);
    sts64(sb + SM_A + aoff,
          pack_h2(__float2half_rn(av.x), __float2half_rn(av.y)),
          pack_h2(__float2half_rn(av.z), __float2half_rn(av.w)));
    av = *(const float4*)(aptr + 32);
    mbar_wait(sb + SM_MBAR, 0);
    __syncthreads();

    for (int ch = 0; ch < 16; ch++) {
        int cur = ch & 1, nxt = cur ^ 1;
        // issue bulk B(ch+1) into the stage freed by MMA(ch-1); store A(ch+1)
        if (ch < 15) {
            if (tid == 0) {
                uint32_t mb = sb + SM_MBAR + (uint32_t)nxt * 8;
                mbar_expect_tx(mb, SB_SZ);
                cp_bulk(sb + (nxt ? SM_SB1 : SM_SB0),
                        WhT + (size_t)(ch + 1) * WE_CH, SB_SZ, mb);
            }
            sts64(sb + SM_A + (uint32_t)nxt * A_SZ + aoff,
                  pack_h2(__float2half_rn(av.x), __float2half_rn(av.y)),
                  pack_h2(__float2half_rn(av.z), __float2half_rn(av.w)));
            if (ch < 14) av = *(const float4*)(aptr + (ch + 2) * 32);
        }

        uint32_t sbB = sb + (cur ? SM_SB1 : SM_SB0);
        uint32_t sA  = sb + SM_A + (uint32_t)cur * A_SZ;
#pragma unroll
        for (int kk = 0; kk < 2; kk++) {
            uint32_t b[4][4];
#pragma unroll
            for (int np = 0; np < 4; np++) {
                int n   = wn * 64 + np * 16 + (lane & 7) + ((lane >> 4) << 3);
                int kel = kk * 16 + (((lane >> 3) & 1) << 3);
                ldm_x4(sbB + (uint32_t)(n * BST + kel) * 2,
                       b[np][0], b[np][1], b[np][2], b[np][3]);
            }
            uint32_t a[2][4];
            int kel = kk * 16 + ((lane >> 4) << 3);
#pragma unroll
            for (int mt = 0; mt < 2; mt++) {
                int row = mt * 16 + (lane & 15);
                ldm_x4(sA + (uint32_t)(row * BST + kel) * 2,
                       a[mt][0], a[mt][1], a[mt][2], a[mt][3]);
            }
#pragma unroll
            for (int mt = 0; mt < 2; mt++)
#pragma unroll
                for (int np = 0; np < 4; np++) {
                    mma_f16(acc[mt][np * 2],     a[mt][0], a[mt][1], a[mt][2], a[mt][3],
                            b[np][0], b[np][1]);
                    mma_f16(acc[mt][np * 2 + 1], a[mt][0], a[mt][1], a[mt][2], a[mt][3],
                            b[np][2], b[np][3]);
                }
        }
        // wait for next B stage; barrier also publishes A(ch+1) stores
        if (ch < 15)
            mbar_wait(sb + SM_MBAR + (uint32_t)nxt * 8, ((ch + 1) >> 1) & 1);
        __syncthreads();
    }

    // ---- fused epilogue ----
    float2* s_red = (float2*)(smc + SM_RED);     // [row 0..31][wn 0..7]
    int r0 = lane >> 2;
    int c0 = wn * 64 + (lane & 3) * 2;
    int bI = rowBase >> 12, iI = (rowBase >> 6) & 63;
    const float* vix = g_Vix + (size_t)((bI << 6) + iI) * CD;

#pragma unroll
    for (int mt = 0; mt < 2; mt++)
#pragma unroll
        for (int h = 0; h < 2; h++) {
            int rloc = mt * 16 + h * 8 + r0;
            int grow = rowBase + rloc;
            const float* vjx = g_Vjx + (size_t)((bI << 6) + (grow & 63)) * CD;
            float sum = 0.f, ss = 0.f;
#pragma unroll
            for (int nt = 0; nt < 8; nt++) {
                int c = c0 + nt * 8;
                float2 vi = *(const float2*)&vix[c];
                float2 vj = *(const float2*)&vjx[c];
                float m0 = acc[mt][nt][h * 2 + 0] + vi.x + vj.x;
                float m1 = acc[mt][nt][h * 2 + 1] + vi.y + vj.y;
                acc[mt][nt][h * 2 + 0] = m0;
                acc[mt][nt][h * 2 + 1] = m1;
                sum += m0 + m1;
                ss  += m0 * m0 + m1 * m1;
            }
            sum += __shfl_xor_sync(0xffffffffu, sum, 1);
            sum += __shfl_xor_sync(0xffffffffu, sum, 2);
            ss  += __shfl_xor_sync(0xffffffffu, ss, 1);
            ss  += __shfl_xor_sync(0xffffffffu, ss, 2);
            if ((lane & 3) == 0) s_red[rloc * 8 + wn] = make_float2(sum, ss);
        }
    __syncthreads();

#pragma unroll
    for (int mt = 0; mt < 2; mt++)
#pragma unroll
        for (int h = 0; h < 2; h++) {
            int rloc = mt * 16 + h * 8 + r0;
            int grow = rowBase + rloc;
            float sum = 0.f, ss = 0.f;
#pragma unroll
            for (int w = 0; w < 8; w++) {
                float2 pp = s_red[rloc * 8 + w];
                sum += pp.x; ss += pp.y;
            }
            float mean = sum * (1.f / CD);
            float var  = ss * (1.f / CD) - mean * mean;
            float inv  = rsqrtf(var + 1e-5f);
            const float* ein = Ein  + (size_t)grow * CD;
            float*       eo  = Eout + (size_t)grow * CD;
#pragma unroll
            for (int nt = 0; nt < 8; nt++) {
                int c = c0 + nt * 8;
                float2 g  = *(const float2*)&ge[c];
                float2 bb = *(const float2*)&be[c];
                float2 e  = *(const float2*)&ein[c];
                float2 o;
                o.x = e.x + fmaxf((acc[mt][nt][h * 2 + 0] - mean) * inv * g.x + bb.x, 0.f);
                o.y = e.y + fmaxf((acc[mt][nt][h * 2 + 1] - mean) * inv * g.y + bb.y, 0.f);
                *(float2*)&eo[c] = o;
            }
        }
}

// ============== fused softmax-over-j + agg + x LN update ====================
extern "C" __global__ void __launch_bounds__(256)
softmax_x_kernel(const float* __restrict__ E, const float* __restrict__ xres,
                 const float* __restrict__ gv, const float* __restrict__ bv,
                 float* __restrict__ xout) {
    __shared__ float s_sum[8], s_ss[8];
    int bi = blockIdx.x;
    int b  = bi >> 6;
    int c  = threadIdx.x;
    const float* ep = E     + (size_t)bi * NN * CD + c;
    const float* up = g_Ujx + (size_t)b  * NN * CD + c;
    float se0 = 0.f, sw0 = 0.f, se1 = 0.f, sw1 = 0.f;
#pragma unroll 4
    for (int j = 0; j < NN; j++) {
        float v0  = ep[(size_t)j * CD];
        float v1  = ep[(size_t)j * CD + 256];
        float sg0 = __fdividef(1.f, 1.f + __expf(-v0));
        float sg1 = __fdividef(1.f, 1.f + __expf(-v1));
        float e0  = __expf(sg0);
        float e1  = __expf(sg1);
        se0 += e0; se1 += e1;
        sw0 = fmaf(e0, up[(size_t)j * CD], sw0);
        sw1 = fmaf(e1, up[(size_t)j * CD + 256], sw1);
    }
    const float* a = g_xWU + (size_t)bi * CD;
    float t0 = a[c]       + __fdividef(sw0, se0 * (float)NN);
    float t1 = a[c + 256] + __fdividef(sw1, se1 * (float)NN);

    float sum = warp_sum(t0 + t1);
    float ss  = warp_sum(t0 * t0 + t1 * t1);
    int lane = c & 31, wid = c >> 5;
    if (lane == 0) { s_sum[wid] = sum; s_ss[wid] = ss; }
    __syncthreads();
    sum = 0.f; ss = 0.f;
#pragma unroll
    for (int w = 0; w < 8; w++) { sum += s_sum[w]; ss += s_ss[w]; }
    float mean = sum * (1.f / CD);
    float var  = ss * (1.f / CD) - mean * mean;
    float inv  = rsqrtf(var + 1e-5f);
    const float* r = xres + (size_t)bi * CD;
    float*       o = xout + (size_t)bi * CD;
    float v0 = (t0 - mean) * inv * gv[c]       + bv[c];
    float v1 = (t1 - mean) * inv * gv[c + 256] + bv[c + 256];
    o[c]       = fmaxf(r[c]       + v0, 0.f);
    o[c + 256] = fmaxf(r[c + 256] + v1, 0.f);
}

// ===========================================================================
extern "C" void kernel_launch(void* const* d_in, const int* in_sizes, int n_in,
                              void* d_out, int out_size) {
    const float* x    = (const float*)d_in[0];
    const float* edge = (const float*)d_in[1];
    const float* WA1  = (const float*)d_in[2];
    const float* WB1  = (const float*)d_in[3];
    const float* WE1  = (const float*)d_in[4];
    const float* WU1  = (const float*)d_in[5];
    const float* WV1  = (const float*)d_in[6];
    const float* WA2  = (const float*)d_in[7];
    const float* WB2  = (const float*)d_in[8];
    const float* WE2  = (const float*)d_in[9];
    const float* WU2  = (const float*)d_in[10];
    const float* WV2  = (const float*)d_in[11];
    const float* ge1  = (const float*)d_in[12];
    const float* gv1  = (const float*)d_in[13];
    const float* ge2  = (const float*)d_in[14];
    const float* gv2  = (const float*)d_in[15];
    const float* be1  = (const float*)d_in[16];
    const float* bv1  = (const float*)d_in[17];
    const float* be2  = (const float*)d_in[18];
    const float* bv2  = (const float*)d_in[19];

    float* xout = (float*)d_out;
    float* eout = (float*)d_out + XEL;

    void* p = nullptr;
    cudaGetSymbolAddress(&p, g_x1);  float* x1 = (float*)p;
    cudaGetSymbolAddress(&p, g_wh);  __half* wh  = (__half*)p;
    cudaGetSymbolAddress(&p, g_weT); __half* weT = (__half*)p;

    cudaFuncSetAttribute(edge_fused_kernel,
                         cudaFuncAttributeMaxDynamicSharedMemorySize, SMEM_EDGE);

    wsplit10_kernel<<<dim3(WSZ / 256, 10), 256>>>(WE1, WE2,
        WA1, WB1, WV1, WU1, WA2, WB2, WV2, WU2);
    wsplit_we_kernel<<<dim3(WSZ / 256, 2), 256>>>(WE1, WE2);

    // ---- layer 1 ----
    x_gemm_kernel<<<dim3(XROWS / 128, 16), 256>>>(x, wh + 2 * (size_t)WSZ);
    edge_fused_kernel<<<EROWS / 32, 256, SMEM_EDGE>>>(edge, weT, ge1, be1, eout);
    softmax_x_kernel<<<XROWS, 256>>>(eout, x, gv1, bv1, x1);

    // ---- layer 2 (edge path in place on eout) ----
    x_gemm_kernel<<<dim3(XROWS / 128, 16), 256>>>(x1, wh + 6 * (size_t)WSZ);
    edge_fused_kernel<<<EROWS / 32, 256, SMEM_EDGE>>>(eout, weT + 16 * (size_t)WE_CH,
                                                      ge2, be2, eout);
    softmax_x_kernel<<<XROWS, 256>>>(eout, x1, gv2, bv2, xout);
}